// round 8
// baseline (speedup 1.0000x reference)
#include <cuda_runtime.h>

// assignments [512, 8192] int32 -> frequency [512, 50257] float32.
#define VOCAB   50257
#define WORDS   ((VOCAB + 1) / 2)   // 25129 packed words (2 x u16 counters each)
#define SEQ     8192
#define THREADS 1024

// Packed-counter histogram: bin v lives in word v>>1, half (v&1).
// Counts <= 8192 < 2^16, so the low half can never carry into the high half;
// a single 32-bit atomicAdd with addend 1 or 65536 is exact.
// smem = 25129*4 = 98.2 KB  ->  2 CTAs/SM: one CTA's atomic phase overlaps the
// other's zero/readout/DRAM phases, keeping the LSU saturated.
__global__ __launch_bounds__(THREADS, 2)
void XTermFrequency_hist_kernel(const int* __restrict__ assign,
                                float* __restrict__ out) {
    extern __shared__ unsigned int s_hist[];

    const int b   = blockIdx.x;
    const int tid = threadIdx.x;

    // 1) Zero packed histogram (25 iters/thread).
    for (int i = tid; i < WORDS; i += THREADS) {
        s_hist[i] = 0u;
    }
    __syncthreads();

    // 2) Histogram: LDG.128 the row, one 32-bit smem atomic per token.
    const int4* __restrict__ row =
        reinterpret_cast<const int4*>(assign + (size_t)b * SEQ);
    #pragma unroll
    for (int i = tid; i < SEQ / 4; i += THREADS) {
        const int4 v = row[i];
        atomicAdd(&s_hist[v.x >> 1], 1u << ((v.x & 1) << 4));
        atomicAdd(&s_hist[v.y >> 1], 1u << ((v.y & 1) << 4));
        atomicAdd(&s_hist[v.z >> 1], 1u << ((v.z & 1) << 4));
        atomicAdd(&s_hist[v.w >> 1], 1u << ((v.w & 1) << 4));
    }
    __syncthreads();

    // 3) Unpack + scale + stream out. Row sum is exactly SEQ, and 1/8192 is a
    //    power of two -> count * inv is exact in fp32.
    float* __restrict__ orow = out + (size_t)b * VOCAB;
    const float inv = 1.0f / (float)SEQ;

    // Row base address is 8B-aligned iff 50257*b is even, i.e. b even.
    if ((b & 1) == 0) {
        float2* __restrict__ o2 = reinterpret_cast<float2*>(orow);
        // 25128 full pairs (bins 0..50255) as STG.64.
        for (int w = tid; w < VOCAB / 2; w += THREADS) {
            const unsigned int c = s_hist[w];
            o2[w] = make_float2((float)(c & 0xFFFFu) * inv,
                                (float)(c >> 16)     * inv);
        }
        if (tid == 0) {  // tail bin 50256 = low half of word 25128
            orow[VOCAB - 1] = (float)(s_hist[WORDS - 1] & 0xFFFFu) * inv;
        }
    } else {
        // Misaligned row: scalar STG.32 pairs.
        for (int w = tid; w < WORDS; w += THREADS) {
            const unsigned int c = s_hist[w];
            const int v = 2 * w;
            orow[v] = (float)(c & 0xFFFFu) * inv;
            if (v + 1 < VOCAB) {
                orow[v + 1] = (float)(c >> 16) * inv;
            }
        }
    }
}

extern "C" void kernel_launch(void* const* d_in, const int* in_sizes, int n_in,
                              void* d_out, int out_size) {
    const int* assign = (const int*)d_in[0];   // [batch, SEQ] int32
    float*     out    = (float*)d_out;         // [batch, VOCAB] float32

    const int batch = in_sizes[0] / SEQ;                     // 512
    const size_t smem_bytes = (size_t)WORDS * sizeof(unsigned int);  // 98.2 KB

    cudaFuncSetAttribute(XTermFrequency_hist_kernel,
                         cudaFuncAttributeMaxDynamicSharedMemorySize,
                         (int)smem_bytes);

    XTermFrequency_hist_kernel<<<batch, THREADS, smem_bytes>>>(assign, out);
}